// round 12
// baseline (speedup 1.0000x reference)
#include <cuda_runtime.h>
#include <cuda_fp16.h>
#include <cstdint>
#include <cstddef>

#define B_TOT 512
#define IC    1152
#define CD    160
#define KD    8
#define NC    10

// ---------------- scratch (device globals; no runtime allocation) ----------
__device__ __half g_uhat[(size_t)B_TOT * IC * CD];   // 188 MB, fp16
__device__ float  g_s[3 * B_TOT * CD];               // s1 | s2 | s3

// ---------------- f32x2 packed-math helpers (sm_103a) ----------------------
typedef unsigned long long ull;
__device__ __forceinline__ ull pack2(float lo, float hi) {
    ull r; asm("mov.b64 %0, {%1, %2};" : "=l"(r) : "f"(lo), "f"(hi)); return r;
}
__device__ __forceinline__ void unpack2(ull p, float& lo, float& hi) {
    asm("mov.b64 {%0, %1}, %2;" : "=f"(lo), "=f"(hi) : "l"(p));
}
__device__ __forceinline__ ull fma2(ull a, ull b, ull c) {
    ull d; asm("fma.rn.f32x2 %0, %1, %2, %3;" : "=l"(d) : "l"(a), "l"(b), "l"(c)); return d;
}
__device__ __forceinline__ ull add2(ull a, ull b) {
    ull d; asm("add.rn.f32x2 %0, %1, %2;" : "=l"(d) : "l"(a), "l"(b)); return d;
}

// ---------------- K1: u_hat = einsum('icdk,bik->bicd') + s1 partials -------
// (unchanged from the 202.8us champion)
#define BT 32
#define IT 12
#define K1_THREADS 320
#define USTRIDE 100
#define K1_SMEM_FLOATS (BT*USTRIDE + IT*KD*CD)   // 18560 floats = 74.2 KB

__global__ void __launch_bounds__(K1_THREADS, 2)
k_uhat(const float* __restrict__ u, const float* __restrict__ W) {
    extern __shared__ float sm[];
    float* u_s = sm;                    // [BT][USTRIDE]
    float* w_s = sm + BT * USTRIDE;     // [IT][8][160]

    const int tid = threadIdx.x;
    const int b0  = blockIdx.x * BT;
    const int i0  = blockIdx.y * IT;

    for (int idx = tid; idx < BT * IT * KD; idx += K1_THREADS) {
        int bl = idx / (IT * KD);
        int r  = idx - bl * (IT * KD);
        u_s[bl * USTRIDE + r] =
            u[(size_t)(b0 + bl) * (IC * KD) + (size_t)i0 * KD + r];
    }
    for (int row = tid; row < IT * CD; row += K1_THREADS) {
        int il = row / CD, cd = row - il * CD;
        const float4 wa = *(const float4*)&W[((size_t)(i0 + il) * CD + cd) * KD];
        const float4 wb = *(const float4*)&W[((size_t)(i0 + il) * CD + cd) * KD + 4];
        float* dst = &w_s[il * (KD * CD) + cd];
        dst[0*CD] = wa.x; dst[1*CD] = wa.y; dst[2*CD] = wa.z; dst[3*CD] = wa.w;
        dst[4*CD] = wb.x; dst[5*CD] = wb.y; dst[6*CD] = wb.z; dst[7*CD] = wb.w;
    }
    __syncthreads();

    const int bh  = tid & 7;
    const int cdq = tid >> 3;
    const int cd0 = cdq * 4;

    ull sacc01[4], sacc23[4];
#pragma unroll
    for (int x = 0; x < 4; x++) { sacc01[x] = 0ull; sacc23[x] = 0ull; }

#pragma unroll 1
    for (int il = 0; il < IT; il++) {
        ull wlo[8], whi[8];
#pragma unroll
        for (int k = 0; k < 8; k++) {
            const float4 wv = *(const float4*)&w_s[(il * KD + k) * CD + cd0];
            wlo[k] = pack2(wv.x, wv.y);
            whi[k] = pack2(wv.z, wv.w);
        }
        const int ig = i0 + il;
#pragma unroll
        for (int bb = 0; bb < 4; bb++) {
            const int bl = bb * 8 + bh;
            const float4 ua = *(const float4*)&u_s[bl * USTRIDE + il * KD];
            const float4 ub = *(const float4*)&u_s[bl * USTRIDE + il * KD + 4];
            ull a01 = 0ull, a23 = 0ull, p;
            p = pack2(ua.x, ua.x); a01 = fma2(wlo[0], p, a01); a23 = fma2(whi[0], p, a23);
            p = pack2(ua.y, ua.y); a01 = fma2(wlo[1], p, a01); a23 = fma2(whi[1], p, a23);
            p = pack2(ua.z, ua.z); a01 = fma2(wlo[2], p, a01); a23 = fma2(whi[2], p, a23);
            p = pack2(ua.w, ua.w); a01 = fma2(wlo[3], p, a01); a23 = fma2(whi[3], p, a23);
            p = pack2(ub.x, ub.x); a01 = fma2(wlo[4], p, a01); a23 = fma2(whi[4], p, a23);
            p = pack2(ub.y, ub.y); a01 = fma2(wlo[5], p, a01); a23 = fma2(whi[5], p, a23);
            p = pack2(ub.z, ub.z); a01 = fma2(wlo[6], p, a01); a23 = fma2(whi[6], p, a23);
            p = pack2(ub.w, ub.w); a01 = fma2(wlo[7], p, a01); a23 = fma2(whi[7], p, a23);
            sacc01[bb] = add2(sacc01[bb], a01);
            sacc23[bb] = add2(sacc23[bb], a23);
            float f0, f1, f2, f3;
            unpack2(a01, f0, f1); unpack2(a23, f2, f3);
            __half2 pa = __floats2half2_rn(f0, f1);
            __half2 pb = __floats2half2_rn(f2, f3);
            ull payload = ((ull)*reinterpret_cast<unsigned*>(&pb) << 32)
                        |  (ull)*reinterpret_cast<unsigned*>(&pa);
            __half* dst = &g_uhat[((size_t)(b0 + bl) * IC + ig) * CD + cd0];
            asm volatile("st.global.cs.b64 [%0], %1;" :: "l"(dst), "l"(payload) : "memory");
        }
    }
#pragma unroll
    for (int bb = 0; bb < 4; bb++) {
        float f0, f1, f2, f3;
        unpack2(sacc01[bb], f0, f1); unpack2(sacc23[bb], f2, f3);
        float* so = &g_s[(size_t)(b0 + bb * 8 + bh) * CD + cd0];
        atomicAdd(&so[0], f0); atomicAdd(&so[1], f1);
        atomicAdd(&so[2], f2); atomicAdd(&so[3], f3);
    }
}

// ---------------- final squash ----------------------------------------------
__global__ void k_squash(const float* __restrict__ s, float* __restrict__ v) {
    const int idx = blockIdx.x * blockDim.x + threadIdx.x;
    if (idx >= B_TOT * NC) return;
    float vals[16];
    const float4* s4 = (const float4*)(s + (size_t)idx * 16);
    float n2 = 0.f;
#pragma unroll
    for (int q = 0; q < 4; q++) {
        float4 t = s4[q];
        vals[4*q+0] = t.x; vals[4*q+1] = t.y; vals[4*q+2] = t.z; vals[4*q+3] = t.w;
        n2 += t.x*t.x + t.y*t.y + t.z*t.z + t.w*t.w;
    }
    const float f = (n2 / (1.f + n2)) / (sqrtf(n2) + 1e-8f);
    float4* v4 = (float4*)(v + (size_t)idx * 16);
#pragma unroll
    for (int q = 0; q < 4; q++)
        v4[q] = make_float4(f*vals[4*q], f*vals[4*q+1], f*vals[4*q+2], f*vals[4*q+3]);
}

// ---------------- routing pass (slim regs, occ 4, NSPL 6) -------------------
__device__ __forceinline__ float ex2a(float x) { float y; asm("ex2.approx.f32 %0, %1;" : "=f"(y) : "f"(x)); return y; }
__device__ __forceinline__ float rcpa(float x) { float y; asm("rcp.approx.f32 %0, %1;" : "=f"(y) : "f"(x)); return y; }

#define NSPL 6
#define RT_THREADS 256

template <int MODE>   // 1: v1 only, 2: v1+v2 combined
__global__ void __launch_bounds__(RT_THREADS, 4)
k_route(const float* __restrict__ s_in1, const float* __restrict__ s_in2,
        float* __restrict__ s_out) {
    __shared__ float4 vcs[40];
    __shared__ float  ssum[CD];

    const int b      = blockIdx.x;
    const int isplit = blockIdx.y;
    const int tid  = threadIdx.x;
    const int warp = tid >> 5, lane = tid & 31;
    const int grp = lane >> 3, sub = lane & 7;

    if (tid < CD) ssum[tid] = 0.f;

    if (tid < 10) {
        float vc[16]; float n2 = 0.f;
#pragma unroll
        for (int d = 0; d < 16; d++) {
            vc[d] = s_in1[(size_t)b * CD + tid * 16 + d] * 0.1f;
            n2 += vc[d] * vc[d];
        }
        const float fa = (n2 / (1.f + n2)) / (sqrtf(n2) + 1e-8f);
#pragma unroll
        for (int d = 0; d < 16; d++) vc[d] *= fa;
        if (MODE == 2) {
            float vb[16]; float m2 = 0.f;
#pragma unroll
            for (int d = 0; d < 16; d++) {
                vb[d] = s_in2[(size_t)b * CD + tid * 16 + d];
                m2 += vb[d] * vb[d];
            }
            const float fb = (m2 / (1.f + m2)) / (sqrtf(m2) + 1e-8f);
#pragma unroll
            for (int d = 0; d < 16; d++) vc[d] += fb * vb[d];
        }
#pragma unroll
        for (int q = 0; q < 4; q++)
            vcs[tid * 4 + q] = make_float4(vc[4*q], vc[4*q+1], vc[4*q+2], vc[4*q+3]);
    }
    __syncthreads();

    const uint2* uh_2 = (const uint2*)g_uhat;

    float4 vr[5];
#pragma unroll
    for (int j = 0; j < 5; j++) vr[j] = vcs[sub + 8 * j];

    float4 sacc[5];
#pragma unroll
    for (int j = 0; j < 5; j++) sacc[j] = make_float4(0.f, 0.f, 0.f, 0.f);

    const int iper = IC / NSPL;          // 192 -> 6 t-iters of 32 i
#pragma unroll 3
    for (int t = 0; t < iper / 32; t++) {
        const int i = isplit * iper + t * 32 + warp * 4 + grp;
        const size_t base = (size_t)(b * IC + i) * 40;
        uint2 q[5];
#pragma unroll
        for (int j = 0; j < 5; j++) q[j] = __ldcs(&uh_2[base + sub + 8 * j]);
        float e[5]; float esum = 0.f;
#pragma unroll
        for (int j = 0; j < 5; j++) {
            const float2 f0 = __half22float2(*reinterpret_cast<const __half2*>(&q[j].x));
            const float2 f1 = __half22float2(*reinterpret_cast<const __half2*>(&q[j].y));
            float d = f0.x * vr[j].x + f0.y * vr[j].y
                    + f1.x * vr[j].z + f1.y * vr[j].w;
            d += __shfl_xor_sync(0xffffffffu, d, 1);
            d += __shfl_xor_sync(0xffffffffu, d, 2);
            e[j] = ex2a(d * 1.4426950408889634f);
            esum += e[j];
        }
        const float tot = esum + __shfl_xor_sync(0xffffffffu, esum, 4);
        const float r = rcpa(tot);
#pragma unroll
        for (int j = 0; j < 5; j++) {
            const float cw = e[j] * r;
            const float2 f0 = __half22float2(*reinterpret_cast<const __half2*>(&q[j].x));
            const float2 f1 = __half22float2(*reinterpret_cast<const __half2*>(&q[j].y));
            sacc[j].x += cw * f0.x; sacc[j].y += cw * f0.y;
            sacc[j].z += cw * f1.x; sacc[j].w += cw * f1.y;
        }
    }

    // hierarchical reduction: warp (over grp) -> smem -> 160 global atomics
#pragma unroll
    for (int j = 0; j < 5; j++) {
        sacc[j].x += __shfl_xor_sync(0xffffffffu, sacc[j].x, 8);
        sacc[j].x += __shfl_xor_sync(0xffffffffu, sacc[j].x, 16);
        sacc[j].y += __shfl_xor_sync(0xffffffffu, sacc[j].y, 8);
        sacc[j].y += __shfl_xor_sync(0xffffffffu, sacc[j].y, 16);
        sacc[j].z += __shfl_xor_sync(0xffffffffu, sacc[j].z, 8);
        sacc[j].z += __shfl_xor_sync(0xffffffffu, sacc[j].z, 16);
        sacc[j].w += __shfl_xor_sync(0xffffffffu, sacc[j].w, 8);
        sacc[j].w += __shfl_xor_sync(0xffffffffu, sacc[j].w, 16);
    }
    if (grp == 0) {
#pragma unroll
        for (int j = 0; j < 5; j++) {
            const int cdb = 4 * (sub + 8 * j);
            atomicAdd(&ssum[cdb + 0], sacc[j].x);
            atomicAdd(&ssum[cdb + 1], sacc[j].y);
            atomicAdd(&ssum[cdb + 2], sacc[j].z);
            atomicAdd(&ssum[cdb + 3], sacc[j].w);
        }
    }
    __syncthreads();
    if (tid < CD)
        atomicAdd(&s_out[(size_t)b * CD + tid], ssum[tid]);
}

// ---------------- launch -----------------------------------------------------
extern "C" void kernel_launch(void* const* d_in, const int* in_sizes, int n_in,
                              void* d_out, int out_size) {
    const float* u = (const float*)d_in[0];
    const float* W = (const float*)d_in[1];
    if (n_in >= 2 && in_sizes[0] == IC * CD * KD) {   // swap safety
        const float* t = u; u = W; W = t;
    }

    cudaFuncSetAttribute(k_uhat, cudaFuncAttributeMaxDynamicSharedMemorySize,
                         K1_SMEM_FLOATS * (int)sizeof(float));

    void* ps;
    cudaGetSymbolAddress(&ps, g_s);
    float* s1 = (float*)ps;
    float* s2 = s1 + B_TOT * CD;
    float* s3 = s2 + B_TOT * CD;

    cudaMemsetAsync(ps, 0, 3 * B_TOT * CD * sizeof(float), 0);

    // 1) u_hat (fp16) + raw sum over i (iter-0 coupling coeffs are exactly 0.1)
    k_uhat<<<dim3(B_TOT / BT, IC / IT), K1_THREADS,
             K1_SMEM_FLOATS * sizeof(float)>>>(u, W);

    // 2) iter-1: v1 = squash(0.1*s1); logits = <uhat, v1>; s2
    k_route<1><<<dim3(B_TOT, NSPL), RT_THREADS>>>(s1, s1, s2);
    // 3) iter-2: vc = v1 + v2; logits = <uhat, vc>; s3
    k_route<2><<<dim3(B_TOT, NSPL), RT_THREADS>>>(s1, s2, s3);
    // 4) output v = squash(s3)
    const int sq_blocks = (B_TOT * NC + 255) / 256;
    k_squash<<<sq_blocks, 256>>>(s3, (float*)d_out);
}

// round 13
// speedup vs baseline: 1.2713x; 1.2713x over previous
#include <cuda_runtime.h>
#include <cuda_fp16.h>
#include <cstdint>
#include <cstddef>

#define B_TOT 512
#define IC    1152
#define CD    160
#define KD    8
#define NC    10

// ---------------- scratch (device globals; no runtime allocation) ----------
__device__ __half g_uhat[(size_t)B_TOT * IC * CD];   // 188 MB, fp16
__device__ float  g_s[3 * B_TOT * CD];               // s1 | s2 | s3

// ---------------- f32x2 packed-math helpers (sm_103a) ----------------------
typedef unsigned long long ull;
__device__ __forceinline__ ull pack2(float lo, float hi) {
    ull r; asm("mov.b64 %0, {%1, %2};" : "=l"(r) : "f"(lo), "f"(hi)); return r;
}
__device__ __forceinline__ void unpack2(ull p, float& lo, float& hi) {
    asm("mov.b64 {%0, %1}, %2;" : "=f"(lo), "=f"(hi) : "l"(p));
}
__device__ __forceinline__ ull fma2(ull a, ull b, ull c) {
    ull d; asm("fma.rn.f32x2 %0, %1, %2, %3;" : "=l"(d) : "l"(a), "l"(b), "l"(c)); return d;
}

// ---------------- K1: u_hat, coalesced stores, w-in-regs (R10 layout) -------
#define BT 32
#define IT 8
#define K1_THREADS 256
#define W_WORDS (IT * KD * CD)     // 10240
#define USTR 68
#define K1_SMEM_FLOATS (W_WORDS + BT * USTR)   // 12416 words = 49.7 KB

__device__ __forceinline__ ull uhat_quad(const ull* wl, const ull* wh,
                                         float4 ua, float4 ub, ull& a23) {
    ull a01 = 0ull; a23 = 0ull; ull p;
    p = pack2(ua.x, ua.x); a01 = fma2(wl[0], p, a01); a23 = fma2(wh[0], p, a23);
    p = pack2(ua.y, ua.y); a01 = fma2(wl[1], p, a01); a23 = fma2(wh[1], p, a23);
    p = pack2(ua.z, ua.z); a01 = fma2(wl[2], p, a01); a23 = fma2(wh[2], p, a23);
    p = pack2(ua.w, ua.w); a01 = fma2(wl[3], p, a01); a23 = fma2(wh[3], p, a23);
    p = pack2(ub.x, ub.x); a01 = fma2(wl[4], p, a01); a23 = fma2(wh[4], p, a23);
    p = pack2(ub.y, ub.y); a01 = fma2(wl[5], p, a01); a23 = fma2(wh[5], p, a23);
    p = pack2(ub.z, ub.z); a01 = fma2(wl[6], p, a01); a23 = fma2(wh[6], p, a23);
    p = pack2(ub.w, ub.w); a01 = fma2(wl[7], p, a01); a23 = fma2(wh[7], p, a23);
    return a01;
}
__device__ __forceinline__ ull to_payload(ull a01, ull a23) {
    float f0, f1, f2, f3;
    unpack2(a01, f0, f1); unpack2(a23, f2, f3);
    __half2 pa = __floats2half2_rn(f0, f1);
    __half2 pb = __floats2half2_rn(f2, f3);
    return ((ull)*reinterpret_cast<unsigned*>(&pb) << 32)
         |  (ull)*reinterpret_cast<unsigned*>(&pa);
}

__global__ void __launch_bounds__(K1_THREADS, 3)
k_uhat(const float* __restrict__ u, const float* __restrict__ W) {
    extern __shared__ float sm[];
    float* w_s = sm;                 // [il][k][cd]
    float* u_s = sm + W_WORDS;       // [bl][USTR]

    const int tid = threadIdx.x;
    const int b0  = blockIdx.x * BT;
    const int i0  = blockIdx.y * IT;

    for (int idx = tid; idx < BT * IT * KD; idx += K1_THREADS) {
        const int bl = idx >> 6, r = idx & 63;
        u_s[bl * USTR + r] = u[(size_t)(b0 + bl) * (IC * KD) + (size_t)i0 * KD + r];
    }
    for (int row = tid; row < IT * CD; row += K1_THREADS) {
        const int il = row / CD, cd = row - il * CD;
        const float4 wa = *(const float4*)&W[((size_t)(i0 + il) * CD + cd) * KD];
        const float4 wb = *(const float4*)&W[((size_t)(i0 + il) * CD + cd) * KD + 4];
        float* dst = &w_s[il * (KD * CD) + cd];
        dst[0*CD] = wa.x; dst[1*CD] = wa.y; dst[2*CD] = wa.z; dst[3*CD] = wa.w;
        dst[4*CD] = wb.x; dst[5*CD] = wb.y; dst[6*CD] = wb.z; dst[7*CD] = wb.w;
    }
    __syncthreads();

    const int wid = tid >> 5, lane = tid & 31;
    const int il = wid, ig = i0 + il;
    const float* wrow = &w_s[il * (KD * CD)];

    // round 0: cd = lane*4 (0..127); loop all 32 bl -> coalesced 256B stores
    {
        const int cd0 = lane * 4;
        ull wl[8], wh[8];
#pragma unroll
        for (int k = 0; k < 8; k++) {
            const float4 wv = *(const float4*)&wrow[k * CD + cd0];
            wl[k] = pack2(wv.x, wv.y); wh[k] = pack2(wv.z, wv.w);
        }
#pragma unroll 4
        for (int bl = 0; bl < BT; bl++) {
            const float4 ua = *(const float4*)&u_s[bl * USTR + il * KD];
            const float4 ub = *(const float4*)&u_s[bl * USTR + il * KD + 4];
            ull a23; const ull a01 = uhat_quad(wl, wh, ua, ub, a23);
            *reinterpret_cast<ull*>(
                &g_uhat[((size_t)(b0 + bl) * IC + ig) * CD + cd0]) = to_payload(a01, a23);
        }
    }
    // round 1: tail cd 128..159, 4 bl per step
    {
        const int bsub = lane >> 3, cq = lane & 7;
        const int cd0 = 128 + cq * 4;
        ull wl[8], wh[8];
#pragma unroll
        for (int k = 0; k < 8; k++) {
            const float4 wv = *(const float4*)&wrow[k * CD + cd0];
            wl[k] = pack2(wv.x, wv.y); wh[k] = pack2(wv.z, wv.w);
        }
#pragma unroll 2
        for (int st = 0; st < 8; st++) {
            const int bl = st * 4 + bsub;
            const float4 ua = *(const float4*)&u_s[bl * USTR + il * KD];
            const float4 ub = *(const float4*)&u_s[bl * USTR + il * KD + 4];
            ull a23; const ull a01 = uhat_quad(wl, wh, ua, ub, a23);
            *reinterpret_cast<ull*>(
                &g_uhat[((size_t)(b0 + bl) * IC + ig) * CD + cd0]) = to_payload(a01, a23);
        }
    }
}

// ---------------- k_sum: s1[b] += partial sums over i (4-way i-split) -------
#define SSPL 4
__global__ void __launch_bounds__(256)
k_sum(float* __restrict__ s1) {
    __shared__ float part[6][CD];
    const int bl = blockIdx.x;
    const int isplit = blockIdx.y;
    const int t = threadIdx.x;
    const int iper = IC / SSPL;          // 288
    if (t < 240) {
        const int q = t % 40, is = t / 40;
        const uint2* base = (const uint2*)g_uhat + (size_t)bl * IC * 40 + q;
        float a0 = 0.f, a1 = 0.f, a2 = 0.f, a3 = 0.f;
#pragma unroll 4
        for (int k = is; k < iper; k += 6) {
            const uint2 v = __ldcs(&base[(size_t)(isplit * iper + k) * 40]);
            const float2 f0 = __half22float2(*reinterpret_cast<const __half2*>(&v.x));
            const float2 f1 = __half22float2(*reinterpret_cast<const __half2*>(&v.y));
            a0 += f0.x; a1 += f0.y; a2 += f1.x; a3 += f1.y;
        }
        part[is][q * 4 + 0] = a0; part[is][q * 4 + 1] = a1;
        part[is][q * 4 + 2] = a2; part[is][q * 4 + 3] = a3;
    }
    __syncthreads();
    if (t < CD) {
        float s = part[0][t] + part[1][t] + part[2][t]
                + part[3][t] + part[4][t] + part[5][t];
        atomicAdd(&s1[(size_t)bl * CD + t], s);
    }
}

// ---------------- final squash ----------------------------------------------
__global__ void k_squash(const float* __restrict__ s, float* __restrict__ v) {
    const int idx = blockIdx.x * blockDim.x + threadIdx.x;
    if (idx >= B_TOT * NC) return;
    float vals[16];
    const float4* s4 = (const float4*)(s + (size_t)idx * 16);
    float n2 = 0.f;
#pragma unroll
    for (int q = 0; q < 4; q++) {
        float4 t = s4[q];
        vals[4*q+0] = t.x; vals[4*q+1] = t.y; vals[4*q+2] = t.z; vals[4*q+3] = t.w;
        n2 += t.x*t.x + t.y*t.y + t.z*t.z + t.w*t.w;
    }
    const float f = (n2 / (1.f + n2)) / (sqrtf(n2) + 1e-8f);
    float4* v4 = (float4*)(v + (size_t)idx * 16);
#pragma unroll
    for (int q = 0; q < 4; q++)
        v4[q] = make_float4(f*vals[4*q], f*vals[4*q+1], f*vals[4*q+2], f*vals[4*q+3]);
}

// ---------------- routing pass (EXACT 202.8us champion) ---------------------
__device__ __forceinline__ float ex2a(float x) { float y; asm("ex2.approx.f32 %0, %1;" : "=f"(y) : "f"(x)); return y; }
__device__ __forceinline__ float rcpa(float x) { float y; asm("rcp.approx.f32 %0, %1;" : "=f"(y) : "f"(x)); return y; }

#define NSPL 4
#define RT_THREADS 256

template <int MODE>   // 1: v1 only, 2: v1+v2 combined
__global__ void __launch_bounds__(RT_THREADS)
k_route(const float* __restrict__ s_in1, const float* __restrict__ s_in2,
        float* __restrict__ s_out) {
    __shared__ float4 vcs[40];
    __shared__ float  ssum[CD];

    const int b      = blockIdx.x;
    const int isplit = blockIdx.y;
    const int tid  = threadIdx.x;
    const int warp = tid >> 5, lane = tid & 31;
    const int grp = lane >> 3, sub = lane & 7;

    if (tid < CD) ssum[tid] = 0.f;

    if (tid < 10) {
        float vc[16]; float n2 = 0.f;
#pragma unroll
        for (int d = 0; d < 16; d++) {
            vc[d] = s_in1[(size_t)b * CD + tid * 16 + d] * 0.1f;
            n2 += vc[d] * vc[d];
        }
        const float fa = (n2 / (1.f + n2)) / (sqrtf(n2) + 1e-8f);
#pragma unroll
        for (int d = 0; d < 16; d++) vc[d] *= fa;
        if (MODE == 2) {
            float vb[16]; float m2 = 0.f;
#pragma unroll
            for (int d = 0; d < 16; d++) {
                vb[d] = s_in2[(size_t)b * CD + tid * 16 + d];
                m2 += vb[d] * vb[d];
            }
            const float fb = (m2 / (1.f + m2)) / (sqrtf(m2) + 1e-8f);
#pragma unroll
            for (int d = 0; d < 16; d++) vc[d] += fb * vb[d];
        }
#pragma unroll
        for (int q = 0; q < 4; q++)
            vcs[tid * 4 + q] = make_float4(vc[4*q], vc[4*q+1], vc[4*q+2], vc[4*q+3]);
    }
    __syncthreads();

    const uint2* uh_2 = (const uint2*)g_uhat;

    float4 vr[5];
#pragma unroll
    for (int j = 0; j < 5; j++) vr[j] = vcs[sub + 8 * j];

    float4 sacc[5];
#pragma unroll
    for (int j = 0; j < 5; j++) sacc[j] = make_float4(0.f, 0.f, 0.f, 0.f);

    const int iper = IC / NSPL;          // 288;  9 rounds of 32 i
#pragma unroll 3
    for (int t = 0; t < iper / 32; t++) {
        const int i = isplit * iper + t * 32 + warp * 4 + grp;
        const size_t base = (size_t)(b * IC + i) * 40;
        uint2 q[5];
#pragma unroll
        for (int j = 0; j < 5; j++) q[j] = __ldcs(&uh_2[base + sub + 8 * j]);
        float4 uh[5];
        float e[5]; float esum = 0.f;
#pragma unroll
        for (int j = 0; j < 5; j++) {
            float2 f0 = __half22float2(*reinterpret_cast<const __half2*>(&q[j].x));
            float2 f1 = __half22float2(*reinterpret_cast<const __half2*>(&q[j].y));
            uh[j] = make_float4(f0.x, f0.y, f1.x, f1.y);
            float d = uh[j].x * vr[j].x + uh[j].y * vr[j].y
                    + uh[j].z * vr[j].z + uh[j].w * vr[j].w;
            d += __shfl_xor_sync(0xffffffffu, d, 1);
            d += __shfl_xor_sync(0xffffffffu, d, 2);
            e[j] = ex2a(d * 1.4426950408889634f);
            esum += e[j];
        }
        const float tot = esum + __shfl_xor_sync(0xffffffffu, esum, 4);
        const float r = rcpa(tot);
#pragma unroll
        for (int j = 0; j < 5; j++) {
            const float cw = e[j] * r;
            sacc[j].x += cw * uh[j].x; sacc[j].y += cw * uh[j].y;
            sacc[j].z += cw * uh[j].z; sacc[j].w += cw * uh[j].w;
        }
    }

#pragma unroll
    for (int j = 0; j < 5; j++) {
        sacc[j].x += __shfl_xor_sync(0xffffffffu, sacc[j].x, 8);
        sacc[j].x += __shfl_xor_sync(0xffffffffu, sacc[j].x, 16);
        sacc[j].y += __shfl_xor_sync(0xffffffffu, sacc[j].y, 8);
        sacc[j].y += __shfl_xor_sync(0xffffffffu, sacc[j].y, 16);
        sacc[j].z += __shfl_xor_sync(0xffffffffu, sacc[j].z, 8);
        sacc[j].z += __shfl_xor_sync(0xffffffffu, sacc[j].z, 16);
        sacc[j].w += __shfl_xor_sync(0xffffffffu, sacc[j].w, 8);
        sacc[j].w += __shfl_xor_sync(0xffffffffu, sacc[j].w, 16);
    }
    if (grp == 0) {
#pragma unroll
        for (int j = 0; j < 5; j++) {
            const int cdb = 4 * (sub + 8 * j);
            atomicAdd(&ssum[cdb + 0], sacc[j].x);
            atomicAdd(&ssum[cdb + 1], sacc[j].y);
            atomicAdd(&ssum[cdb + 2], sacc[j].z);
            atomicAdd(&ssum[cdb + 3], sacc[j].w);
        }
    }
    __syncthreads();
    if (tid < CD)
        atomicAdd(&s_out[(size_t)b * CD + tid], ssum[tid]);
}

// ---------------- launch -----------------------------------------------------
extern "C" void kernel_launch(void* const* d_in, const int* in_sizes, int n_in,
                              void* d_out, int out_size) {
    const float* u = (const float*)d_in[0];
    const float* W = (const float*)d_in[1];
    if (n_in >= 2 && in_sizes[0] == IC * CD * KD) {   // swap safety
        const float* t = u; u = W; W = t;
    }

    cudaFuncSetAttribute(k_uhat, cudaFuncAttributeMaxDynamicSharedMemorySize,
                         K1_SMEM_FLOATS * (int)sizeof(float));

    void* ps;
    cudaGetSymbolAddress(&ps, g_s);
    float* s1 = (float*)ps;
    float* s2 = s1 + B_TOT * CD;
    float* s3 = s2 + B_TOT * CD;

    cudaMemsetAsync(ps, 0, 3 * B_TOT * CD * sizeof(float), 0);

    // 1) u_hat (fp16), coalesced stores
    k_uhat<<<dim3(B_TOT / BT, IC / IT), K1_THREADS,
             K1_SMEM_FLOATS * sizeof(float)>>>(u, W);
    // 2) s1 = sum_i u_hat (streaming re-read)
    k_sum<<<dim3(B_TOT, SSPL), 256>>>(s1);
    // 3) iter-1: v1 = squash(0.1*s1); s2
    k_route<1><<<dim3(B_TOT, NSPL), RT_THREADS>>>(s1, s1, s2);
    // 4) iter-2: vc = v1 + v2; s3
    k_route<2><<<dim3(B_TOT, NSPL), RT_THREADS>>>(s1, s2, s3);
    // 5) output v = squash(s3)
    const int sq_blocks = (B_TOT * NC + 255) / 256;
    k_squash<<<sq_blocks, 256>>>(s3, (float*)d_out);
}